// round 2
// baseline (speedup 1.0000x reference)
#include <cuda_runtime.h>
#include <math.h>

// Problem-size constants (fixed by the dataset)
#define NN 40000

// ---------------------------------------------------------------------------
// Scratch (device globals; no allocation allowed)
// ---------------------------------------------------------------------------
__device__ float g_xh1[NN * 256];   // x @ gat1_W  [N, 2*128]
__device__ float g_acc1[NN * 256];  // GAT1 accumulator / output
__device__ float g_as1[NN * 2];
__device__ float g_ad1[NN * 2];
__device__ float g_m1[NN * 2];
__device__ float g_s1[NN * 2];
__device__ float g_xh2[NN * 64];    // gat1out @ gat2_W
__device__ float g_acc2[NN * 64];   // GAT2 accumulator / output
__device__ float g_as2[NN];
__device__ float g_ad2[NN];
__device__ float g_m2[NN];
__device__ float g_s2[NN];
__device__ float g_xw1[NN * 128];   // x @ gcn1_W
__device__ float g_gcn1[NN * 128];  // GCN1 accumulator / output
__device__ float g_xw2[NN * 64];    // gcn1out @ gcn2_W
__device__ float g_gcn2[NN * 64];   // GCN2 accumulator / output
__device__ float g_deg[NN];
__device__ float g_dinv[NN];
__device__ float g_cat[NN * 128];
__device__ float g_y1[NN * 256];
__device__ float g_y2[NN * 128];

// ---------------------------------------------------------------------------
// Helpers
// ---------------------------------------------------------------------------
__device__ __forceinline__ void red_add_v4(float4* addr, float x, float y, float z, float w) {
    asm volatile("red.global.add.v4.f32 [%0], {%1,%2,%3,%4};"
                 :: "l"(addr), "f"(x), "f"(y), "f"(z), "f"(w) : "memory");
}

__device__ __forceinline__ void atomicMaxF(float* addr, float v) {
    if (v >= 0.0f)
        atomicMax((int*)addr, __float_as_int(v));
    else
        atomicMin((unsigned int*)addr, __float_as_uint(v));
}

__global__ void fill_kernel(float* p, float v, int n) {
    int i = blockIdx.x * blockDim.x + threadIdx.x;
    int st = gridDim.x * blockDim.x;
    for (; i < n; i += st) p[i] = v;
}

// ---------------------------------------------------------------------------
// GEMM: C[M,Nc] = A[M,K] @ B[K,Nc] (+bias) (+act).  All dims multiples of tile.
// BM=64, BN=64, BK=16, 128 threads, 8x4 per thread.
// ---------------------------------------------------------------------------
#define BM 64
#define BN 64
#define BK 16
__global__ void gemm_kernel(const float* __restrict__ A, const float* __restrict__ B,
                            const float* __restrict__ bias, float* __restrict__ C,
                            int M, int Nc, int K, int act) {
    __shared__ float As[BK][BM + 4];
    __shared__ float Bs[BK][BN];
    const int tx = threadIdx.x;             // 0..127
    const int row0 = blockIdx.y * BM;
    const int col0 = blockIdx.x * BN;
    const int tr = (tx >> 4) * 8;           // 0..56
    const int tc = (tx & 15) * 4;           // 0..60

    float acc[8][4];
#pragma unroll
    for (int i = 0; i < 8; i++)
#pragma unroll
        for (int j = 0; j < 4; j++) acc[i][j] = 0.0f;

    for (int k0 = 0; k0 < K; k0 += BK) {
#pragma unroll
        for (int i = tx; i < BM * BK; i += 128) {
            int r = i >> 4, c = i & 15;
            As[c][r] = A[(size_t)(row0 + r) * K + k0 + c];
        }
#pragma unroll
        for (int i = tx; i < BK * BN; i += 128) {
            int r = i >> 6, c = i & 63;
            Bs[r][c] = B[(size_t)(k0 + r) * Nc + col0 + c];
        }
        __syncthreads();
#pragma unroll
        for (int kk = 0; kk < BK; kk++) {
            float a[8], b[4];
#pragma unroll
            for (int i = 0; i < 8; i++) a[i] = As[kk][tr + i];
#pragma unroll
            for (int j = 0; j < 4; j++) b[j] = Bs[kk][tc + j];
#pragma unroll
            for (int i = 0; i < 8; i++)
#pragma unroll
                for (int j = 0; j < 4; j++) acc[i][j] = fmaf(a[i], b[j], acc[i][j]);
        }
        __syncthreads();
    }
#pragma unroll
    for (int i = 0; i < 8; i++) {
        int row = row0 + tr + i;
#pragma unroll
        for (int j = 0; j < 4; j++) {
            int col = col0 + tc + j;
            float v = acc[i][j];
            if (bias) v += bias[col];
            if (act == 1) v = fmaxf(v, 0.0f);
            else if (act == 2) v = v > 0.0f ? v : expm1f(v);
            C[(size_t)row * Nc + col] = v;
        }
    }
}

// ---------------------------------------------------------------------------
// Attention logits: out_s[w] = <xh[w,:], att_src[w%heads,:]>  (warp per row)
// ---------------------------------------------------------------------------
__global__ void att_kernel(const float* __restrict__ xh, const float* __restrict__ a_src,
                           const float* __restrict__ a_dst, float* __restrict__ out_s,
                           float* __restrict__ out_d, int rows, int heads, int ch) {
    int w = (blockIdx.x * blockDim.x + threadIdx.x) >> 5;
    int lane = threadIdx.x & 31;
    if (w >= rows) return;
    const float* row = xh + (size_t)w * ch;
    const float* as = a_src + (size_t)(w % heads) * ch;
    const float* ad = a_dst + (size_t)(w % heads) * ch;
    float ss = 0.0f, dd = 0.0f;
    for (int c = lane; c < ch; c += 32) {
        float v = row[c];
        ss += v * as[c];
        dd += v * ad[c];
    }
#pragma unroll
    for (int o = 16; o; o >>= 1) {
        ss += __shfl_down_sync(0xFFFFFFFFu, ss, o);
        dd += __shfl_down_sync(0xFFFFFFFFu, dd, o);
    }
    if (lane == 0) { out_s[w] = ss; out_d[w] = dd; }
}

// ---------------------------------------------------------------------------
// Segment-softmax pass 1: per-dst max of leaky_relu(a_s[src]+a_d[dst])
// ---------------------------------------------------------------------------
__global__ void edge_max_kernel(const int* __restrict__ src, const int* __restrict__ dst,
                                const float* __restrict__ as_, const float* __restrict__ ad_,
                                float* __restrict__ m, int heads, int E, int Etot) {
    int t = blockIdx.x * blockDim.x + threadIdx.x;
    if (t >= Etot * heads) return;
    int e = t / heads, h = t - e * heads;
    int s = (e < E) ? src[e] : (e - E);
    int d = (e < E) ? dst[e] : (e - E);
    float v = as_[s * heads + h] + ad_[d * heads + h];
    v = v > 0.0f ? v : 0.2f * v;
    atomicMaxF(&m[d * heads + h], v);
}

// ---------------------------------------------------------------------------
// Segment-softmax pass 2: accumulate sum(a) and sum(a * xh[src]) per dst.
// One warp per edge; float4 vector atomics.
// ---------------------------------------------------------------------------
template <int HEADS, int CH>
__global__ void gat_scatter_kernel(const int* __restrict__ src, const int* __restrict__ dst,
                                   const float* __restrict__ as_, const float* __restrict__ ad_,
                                   const float* __restrict__ m, float* __restrict__ ssum,
                                   const float* __restrict__ xh, float* __restrict__ acc,
                                   int E, int Etot) {
    int w = (blockIdx.x * blockDim.x + threadIdx.x) >> 5;
    int lane = threadIdx.x & 31;
    if (w >= Etot) return;
    int s = (w < E) ? __ldg(&src[w]) : (w - E);
    int d = (w < E) ? __ldg(&dst[w]) : (w - E);
    float a[HEADS];
#pragma unroll
    for (int h = 0; h < HEADS; h++) {
        float v = as_[s * HEADS + h] + ad_[d * HEADS + h];
        v = v > 0.0f ? v : 0.2f * v;
        a[h] = expf(v - m[d * HEADS + h]);
    }
    if (lane == 0) {
#pragma unroll
        for (int h = 0; h < HEADS; h++) atomicAdd(&ssum[d * HEADS + h], a[h]);
    }
    constexpr int NV = HEADS * CH / 4;
    const float4* xs = (const float4*)(xh + (size_t)s * (HEADS * CH));
    float4* ap = (float4*)(acc + (size_t)d * (HEADS * CH));
#pragma unroll
    for (int j = lane; j < NV; j += 32) {
        float sc = a[j / (CH / 4)];
        float4 v = xs[j];
        red_add_v4(ap + j, v.x * sc, v.y * sc, v.z * sc, v.w * sc);
    }
}

// out = acc / (ssum + 1e-16) + bias, optional ELU
__global__ void gat_fin_kernel(float* __restrict__ acc, const float* __restrict__ ssum,
                               const float* __restrict__ bias, int n, int heads, int ch, int act) {
    int t = blockIdx.x * blockDim.x + threadIdx.x;
    int tot = n * heads * ch;
    if (t >= tot) return;
    int hc = t % (heads * ch);
    int node = t / (heads * ch);
    int h = hc / ch;
    float v = acc[t] / (ssum[node * heads + h] + 1e-16f) + bias[hc];
    if (act == 2) v = v > 0.0f ? v : expm1f(v);
    acc[t] = v;
}

// ---------------------------------------------------------------------------
// GCN
// ---------------------------------------------------------------------------
__global__ void deg_kernel(const int* __restrict__ dst, float* __restrict__ deg, int E, int Etot) {
    int t = blockIdx.x * blockDim.x + threadIdx.x;
    if (t >= Etot) return;
    int d = (t < E) ? dst[t] : (t - E);
    atomicAdd(&deg[d], 1.0f);
}

__global__ void dinv_kernel(const float* __restrict__ deg, float* __restrict__ dinv, int n) {
    int t = blockIdx.x * blockDim.x + threadIdx.x;
    if (t >= n) return;
    dinv[t] = rsqrtf(fmaxf(deg[t], 1.0f));
}

template <int CH>
__global__ void gcn_scatter_kernel(const int* __restrict__ src, const int* __restrict__ dst,
                                   const float* __restrict__ dinv, const float* __restrict__ xw,
                                   float* __restrict__ acc, int E, int Etot) {
    int w = (blockIdx.x * blockDim.x + threadIdx.x) >> 5;
    int lane = threadIdx.x & 31;
    if (w >= Etot) return;
    int s = (w < E) ? __ldg(&src[w]) : (w - E);
    int d = (w < E) ? __ldg(&dst[w]) : (w - E);
    float norm = dinv[s] * dinv[d];
    constexpr int NV = CH / 4;
    const float4* xs = (const float4*)(xw + (size_t)s * CH);
    float4* ap = (float4*)(acc + (size_t)d * CH);
#pragma unroll
    for (int j = lane; j < NV; j += 32) {
        float4 v = xs[j];
        red_add_v4(ap + j, v.x * norm, v.y * norm, v.z * norm, v.w * norm);
    }
}

__global__ void bias_act_kernel(float* __restrict__ p, const float* __restrict__ bias,
                                int n, int ch, int act) {
    int t = blockIdx.x * blockDim.x + threadIdx.x;
    if (t >= n * ch) return;
    float v = p[t] + bias[t % ch];
    if (act == 1) v = fmaxf(v, 0.0f);
    p[t] = v;
}

// cat[:, :64] = gcn2 * wc ; cat[:, 64:] = gat2 * wt
__global__ void cat_kernel(const float* __restrict__ gcn, const float* __restrict__ gat,
                           const float* __restrict__ wc, const float* __restrict__ wt,
                           float* __restrict__ cat, int n) {
    int t = blockIdx.x * blockDim.x + threadIdx.x;
    if (t >= n * 128) return;
    int node = t >> 7, c = t & 127;
    cat[t] = (c < 64) ? gcn[node * 64 + c] * wc[0]
                      : gat[node * 64 + (c - 64)] * wt[0];
}

// ---------------------------------------------------------------------------
// Launch
// ---------------------------------------------------------------------------
static inline int cdiv(int a, int b) { return (a + b - 1) / b; }

extern "C" void kernel_launch(void* const* d_in, const int* in_sizes, int n_in,
                              void* d_out, int out_size) {
    const float* x        = (const float*)d_in[0];
    const int*   src      = (const int*)d_in[1];
    const int    E        = in_sizes[1] / 2;
    const int*   dst      = src + E;
    const float* gat1_W   = (const float*)d_in[2];
    const float* att_s1   = (const float*)d_in[3];
    const float* att_d1   = (const float*)d_in[4];
    const float* gat1_b   = (const float*)d_in[5];
    const float* gat2_W   = (const float*)d_in[6];
    const float* att_s2   = (const float*)d_in[7];
    const float* att_d2   = (const float*)d_in[8];
    const float* gat2_b   = (const float*)d_in[9];
    const float* gcn1_W   = (const float*)d_in[10];
    const float* gcn1_b   = (const float*)d_in[11];
    const float* gcn2_W   = (const float*)d_in[12];
    const float* gcn2_b   = (const float*)d_in[13];
    const float* lin1_W   = (const float*)d_in[14];
    const float* lin1_b   = (const float*)d_in[15];
    const float* lin2_W   = (const float*)d_in[16];
    const float* lin2_b   = (const float*)d_in[17];
    const float* lin3_W   = (const float*)d_in[18];
    const float* lin3_b   = (const float*)d_in[19];
    const float* wt       = (const float*)d_in[20];
    const float* wc       = (const float*)d_in[21];

    const int Etot = E + NN;

    float *xh1, *acc1, *as1, *ad1, *m1, *s1;
    float *xh2, *acc2, *as2, *ad2, *m2, *s2;
    float *xw1, *gcn1, *xw2, *gcn2, *deg, *dinv, *cat, *y1, *y2;
    cudaGetSymbolAddress((void**)&xh1, g_xh1);
    cudaGetSymbolAddress((void**)&acc1, g_acc1);
    cudaGetSymbolAddress((void**)&as1, g_as1);
    cudaGetSymbolAddress((void**)&ad1, g_ad1);
    cudaGetSymbolAddress((void**)&m1, g_m1);
    cudaGetSymbolAddress((void**)&s1, g_s1);
    cudaGetSymbolAddress((void**)&xh2, g_xh2);
    cudaGetSymbolAddress((void**)&acc2, g_acc2);
    cudaGetSymbolAddress((void**)&as2, g_as2);
    cudaGetSymbolAddress((void**)&ad2, g_ad2);
    cudaGetSymbolAddress((void**)&m2, g_m2);
    cudaGetSymbolAddress((void**)&s2, g_s2);
    cudaGetSymbolAddress((void**)&xw1, g_xw1);
    cudaGetSymbolAddress((void**)&gcn1, g_gcn1);
    cudaGetSymbolAddress((void**)&xw2, g_xw2);
    cudaGetSymbolAddress((void**)&gcn2, g_gcn2);
    cudaGetSymbolAddress((void**)&deg, g_deg);
    cudaGetSymbolAddress((void**)&dinv, g_dinv);
    cudaGetSymbolAddress((void**)&cat, g_cat);
    cudaGetSymbolAddress((void**)&y1, g_y1);
    cudaGetSymbolAddress((void**)&y2, g_y2);

    const int TB = 256;
    const float NEG_INF = -INFINITY;

    // ---- zero / init accumulators ----
    fill_kernel<<<4096, TB>>>(acc1, 0.0f, NN * 256);
    fill_kernel<<<cdiv(NN * 2, TB), TB>>>(s1, 0.0f, NN * 2);
    fill_kernel<<<cdiv(NN * 2, TB), TB>>>(m1, NEG_INF, NN * 2);
    fill_kernel<<<cdiv(NN * 64, TB), TB>>>(acc2, 0.0f, NN * 64);
    fill_kernel<<<cdiv(NN, TB), TB>>>(s2, 0.0f, NN);
    fill_kernel<<<cdiv(NN, TB), TB>>>(m2, NEG_INF, NN);
    fill_kernel<<<cdiv(NN * 128, TB), TB>>>(gcn1, 0.0f, NN * 128);
    fill_kernel<<<cdiv(NN * 64, TB), TB>>>(gcn2, 0.0f, NN * 64);
    fill_kernel<<<cdiv(NN, TB), TB>>>(deg, 0.0f, NN);

    // ---- dense projections from x ----
    gemm_kernel<<<dim3(256 / BN, NN / BM), 128>>>(x, gat1_W, nullptr, xh1, NN, 256, 128, 0);
    gemm_kernel<<<dim3(128 / BN, NN / BM), 128>>>(x, gcn1_W, nullptr, xw1, NN, 128, 128, 0);

    // ---- degree / norm (shared by both GCN layers) ----
    deg_kernel<<<cdiv(Etot, TB), TB>>>(dst, deg, E, Etot);
    dinv_kernel<<<cdiv(NN, TB), TB>>>(deg, dinv, NN);

    // ---- GAT layer 1 (heads=2, ch=128) ----
    att_kernel<<<cdiv(NN * 2 * 32, TB), TB>>>(xh1, att_s1, att_d1, as1, ad1, NN * 2, 2, 128);
    edge_max_kernel<<<cdiv(Etot * 2, TB), TB>>>(src, dst, as1, ad1, m1, 2, E, Etot);
    gat_scatter_kernel<2, 128><<<cdiv(Etot * 32, TB), TB>>>(src, dst, as1, ad1, m1, s1, xh1, acc1, E, Etot);
    gat_fin_kernel<<<cdiv(NN * 256, TB), TB>>>(acc1, s1, gat1_b, NN, 2, 128, 2 /*elu*/);

    // ---- GAT layer 2 (heads=1, ch=64) ----
    gemm_kernel<<<dim3(64 / BN, NN / BM), 128>>>(acc1, gat2_W, nullptr, xh2, NN, 64, 256, 0);
    att_kernel<<<cdiv(NN * 32, TB), TB>>>(xh2, att_s2, att_d2, as2, ad2, NN, 1, 64);
    edge_max_kernel<<<cdiv(Etot, TB), TB>>>(src, dst, as2, ad2, m2, 1, E, Etot);
    gat_scatter_kernel<1, 64><<<cdiv(Etot * 32, TB), TB>>>(src, dst, as2, ad2, m2, s2, xh2, acc2, E, Etot);
    gat_fin_kernel<<<cdiv(NN * 64, TB), TB>>>(acc2, s2, gat2_b, NN, 1, 64, 0);

    // ---- GCN layer 1 ----
    gcn_scatter_kernel<128><<<cdiv(Etot * 32, TB), TB>>>(src, dst, dinv, xw1, gcn1, E, Etot);
    bias_act_kernel<<<cdiv(NN * 128, TB), TB>>>(gcn1, gcn1_b, NN, 128, 1 /*relu*/);

    // ---- GCN layer 2 ----
    gemm_kernel<<<dim3(64 / BN, NN / BM), 128>>>(gcn1, gcn2_W, nullptr, xw2, NN, 64, 128, 0);
    gcn_scatter_kernel<64><<<cdiv(Etot * 32, TB), TB>>>(src, dst, dinv, xw2, gcn2, E, Etot);
    bias_act_kernel<<<cdiv(NN * 64, TB), TB>>>(gcn2, gcn2_b, NN, 64, 0);

    // ---- concat + MLP head ----
    cat_kernel<<<cdiv(NN * 128, TB), TB>>>(gcn2, acc2, wc, wt, cat, NN);
    gemm_kernel<<<dim3(256 / BN, NN / BM), 128>>>(cat, lin1_W, lin1_b, y1, NN, 256, 128, 0);
    gemm_kernel<<<dim3(128 / BN, NN / BM), 128>>>(y1, lin2_W, lin2_b, y2, NN, 128, 256, 0);
    gemm_kernel<<<dim3(64 / BN, NN / BM), 128>>>(y2, lin3_W, lin3_b, (float*)d_out, NN, 64, 128, 0);
}

// round 7
// speedup vs baseline: 2.1671x; 2.1671x over previous
#include <cuda_runtime.h>
#include <math.h>

#define NN 40000
#define MAXE 700000   // E (640k) + self loops (40k) with slack

// ---------------------------------------------------------------------------
// Scratch (device globals)
// ---------------------------------------------------------------------------
__device__ float g_xh1[NN * 256];   // x @ gat1_W
__device__ float g_acc1[NN * 256];  // GAT1 output
__device__ float g_as1[NN * 2];
__device__ float g_ad1[NN * 2];
__device__ float g_xh2[NN * 64];    // gat1out @ gat2_W
__device__ float g_as2[NN];
__device__ float g_ad2[NN];
__device__ float g_xw1[NN * 128];   // x @ gcn1_W
__device__ float g_gcn1[NN * 128];  // GCN1 output
__device__ float g_xw2[NN * 64];
__device__ float g_dinv[NN];
__device__ float g_cat[NN * 128];   // [gcn2*wc | gat2*wt]
__device__ float g_y1[NN * 256];
__device__ float g_y2[NN * 128];
// CSR scratch
__device__ int g_counts[NN];
__device__ int g_rs[NN + 1];
__device__ int g_cursor[NN];
__device__ int g_csr[MAXE];         // src ids grouped by dst

// ---------------------------------------------------------------------------
// CSR build
// ---------------------------------------------------------------------------
__global__ void zero_int_kernel(int* p, int n) {
    int i = blockIdx.x * blockDim.x + threadIdx.x;
    if (i < n) p[i] = 0;
}

__global__ void hist_kernel(const int* __restrict__ dst, int* __restrict__ counts,
                            int E, int Etot) {
    int t = blockIdx.x * blockDim.x + threadIdx.x;
    if (t >= Etot) return;
    int d = (t < E) ? dst[t] : (t - E);
    atomicAdd(&counts[d], 1);
}

// single-block exclusive scan of 40k counts -> rs, rs[n] = total
__global__ void scan_kernel(const int* __restrict__ counts, int* __restrict__ rs, int n) {
    __shared__ int sums[1024];
    int t = threadIdx.x;
    int per = (n + 1023) >> 10;
    int beg = t * per;
    int end = min(beg + per, n);
    int s = 0;
    for (int i = beg; i < end; i++) s += counts[i];
    sums[t] = s;
    __syncthreads();
    for (int off = 1; off < 1024; off <<= 1) {
        int v = (t >= off) ? sums[t - off] : 0;
        __syncthreads();
        sums[t] += v;
        __syncthreads();
    }
    int base = (t == 0) ? 0 : sums[t - 1];
    for (int i = beg; i < end; i++) { rs[i] = base; base += counts[i]; }
    if (beg < n && end == n) rs[n] = base;
}

__global__ void copy_int_kernel(const int* __restrict__ a, int* __restrict__ b, int n) {
    int i = blockIdx.x * blockDim.x + threadIdx.x;
    if (i < n) b[i] = a[i];
}

__global__ void csr_fill_kernel(const int* __restrict__ src, const int* __restrict__ dst,
                                int* __restrict__ cursor, int* __restrict__ csr,
                                int E, int Etot) {
    int t = blockIdx.x * blockDim.x + threadIdx.x;
    if (t >= Etot) return;
    int s = (t < E) ? src[t] : (t - E);
    int d = (t < E) ? dst[t] : (t - E);
    int pos = atomicAdd(&cursor[d], 1);
    csr[pos] = s;
}

__global__ void dinv_kernel(const int* __restrict__ counts, float* __restrict__ dinv, int n) {
    int t = blockIdx.x * blockDim.x + threadIdx.x;
    if (t >= n) return;
    dinv[t] = rsqrtf(fmaxf((float)counts[t], 1.0f));
}

// ---------------------------------------------------------------------------
// GEMM: C[M,Nc] = A[M,K] @ B[K,Nc] (+bias). M % 160 == 0, Nc % 64 == 0, K % 16 == 0.
// 160x64 tile, BK=16, 320 threads, 8x4 per thread.
// ---------------------------------------------------------------------------
#define GBM 160
#define GBN 64
#define GBK 16
__global__ __launch_bounds__(320) void gemm2_kernel(
        const float* __restrict__ A, const float* __restrict__ B,
        const float* __restrict__ bias, float* __restrict__ C,
        int M, int Nc, int K) {
    __shared__ float As[GBK][GBM + 4];
    __shared__ float Bs[GBK][GBN];
    const int t = threadIdx.x;            // 0..319
    const int row0 = blockIdx.y * GBM;
    const int col0 = blockIdx.x * GBN;
    const int ty = t >> 4;                // 0..19
    const int tx = t & 15;                // 0..15
    const int tr = ty * 8;
    const int tc = tx * 4;

    float acc[8][4];
#pragma unroll
    for (int i = 0; i < 8; i++)
#pragma unroll
        for (int j = 0; j < 4; j++) acc[i][j] = 0.0f;

    for (int k0 = 0; k0 < K; k0 += GBK) {
#pragma unroll
        for (int i = 0; i < 2; i++) {
            int f = t + i * 320;                 // 0..639 float4s of the A tile
            int r = f >> 2, c4 = (f & 3) * 4;
            float4 v = *(const float4*)&A[(size_t)(row0 + r) * K + k0 + c4];
            As[c4 + 0][r] = v.x; As[c4 + 1][r] = v.y;
            As[c4 + 2][r] = v.z; As[c4 + 3][r] = v.w;
        }
        if (t < 256) {
            int r = t >> 4, c4 = (t & 15) * 4;
            float4 v = *(const float4*)&B[(size_t)(k0 + r) * Nc + col0 + c4];
            *(float4*)&Bs[r][c4] = v;
        }
        __syncthreads();
#pragma unroll
        for (int kk = 0; kk < GBK; kk++) {
            float4 b4 = *(float4*)&Bs[kk][tc];
            float a[8];
#pragma unroll
            for (int i = 0; i < 8; i++) a[i] = As[kk][tr + i];
#pragma unroll
            for (int i = 0; i < 8; i++) {
                acc[i][0] = fmaf(a[i], b4.x, acc[i][0]);
                acc[i][1] = fmaf(a[i], b4.y, acc[i][1]);
                acc[i][2] = fmaf(a[i], b4.z, acc[i][2]);
                acc[i][3] = fmaf(a[i], b4.w, acc[i][3]);
            }
        }
        __syncthreads();
    }
    float4 bb = make_float4(0.f, 0.f, 0.f, 0.f);
    if (bias) bb = *(const float4*)&bias[col0 + tc];
#pragma unroll
    for (int i = 0; i < 8; i++) {
        float4 o;
        o.x = acc[i][0] + bb.x; o.y = acc[i][1] + bb.y;
        o.z = acc[i][2] + bb.z; o.w = acc[i][3] + bb.w;
        *(float4*)&C[(size_t)(row0 + tr + i) * Nc + col0 + tc] = o;
    }
}

// ---------------------------------------------------------------------------
// Attention logits: per 'row' of xh (row = node*heads + h)
// ---------------------------------------------------------------------------
__global__ void att_kernel(const float* __restrict__ xh, const float* __restrict__ a_src,
                           const float* __restrict__ a_dst, float* __restrict__ out_s,
                           float* __restrict__ out_d, int rows, int heads, int ch) {
    int w = (blockIdx.x * blockDim.x + threadIdx.x) >> 5;
    int lane = threadIdx.x & 31;
    if (w >= rows) return;
    const float* row = xh + (size_t)w * ch;
    const float* as = a_src + (size_t)(w % heads) * ch;
    const float* ad = a_dst + (size_t)(w % heads) * ch;
    float ss = 0.0f, dd = 0.0f;
    for (int c = lane; c < ch; c += 32) {
        float v = row[c];
        ss += v * as[c];
        dd += v * ad[c];
    }
#pragma unroll
    for (int o = 16; o; o >>= 1) {
        ss += __shfl_down_sync(0xFFFFFFFFu, ss, o);
        dd += __shfl_down_sync(0xFFFFFFFFu, dd, o);
    }
    if (lane == 0) { out_s[w] = ss; out_d[w] = dd; }
}

// ---------------------------------------------------------------------------
// GAT pull: one warp per destination node. Fused softmax + aggregate + finalize.
// ---------------------------------------------------------------------------
__global__ __launch_bounds__(256) void gat_pull_2_128(
        const int* __restrict__ rs, const int* __restrict__ csr,
        const float* __restrict__ as_, const float* __restrict__ ad_,
        const float* __restrict__ xh, const float* __restrict__ bias,
        float* __restrict__ out) {
    int d = (blockIdx.x * blockDim.x + threadIdx.x) >> 5;
    int lane = threadIdx.x & 31;
    if (d >= NN) return;
    int beg = rs[d], end = rs[d + 1];
    float ad0 = ad_[d * 2 + 0], ad1 = ad_[d * 2 + 1];
    // pass 1: max logit per head
    float m0 = -INFINITY, m1 = -INFINITY;
    for (int j = beg + lane; j < end; j += 32) {
        int s = __ldg(&csr[j]);
        float l0 = as_[s * 2 + 0] + ad0; l0 = l0 > 0.f ? l0 : 0.2f * l0;
        float l1 = as_[s * 2 + 1] + ad1; l1 = l1 > 0.f ? l1 : 0.2f * l1;
        m0 = fmaxf(m0, l0); m1 = fmaxf(m1, l1);
    }
#pragma unroll
    for (int o = 16; o; o >>= 1) {
        m0 = fmaxf(m0, __shfl_xor_sync(0xFFFFFFFFu, m0, o));
        m1 = fmaxf(m1, __shfl_xor_sync(0xFFFFFFFFu, m1, o));
    }
    // pass 2: exp-sum + weighted feature sum
    float s0 = 0.f, s1 = 0.f;
    float f0[4] = {0.f, 0.f, 0.f, 0.f};
    float f1[4] = {0.f, 0.f, 0.f, 0.f};
    for (int j = beg; j < end; ++j) {
        int s = __ldg(&csr[j]);
        float l0 = as_[s * 2 + 0] + ad0; l0 = l0 > 0.f ? l0 : 0.2f * l0;
        float l1 = as_[s * 2 + 1] + ad1; l1 = l1 > 0.f ? l1 : 0.2f * l1;
        float a0 = __expf(l0 - m0), a1 = __expf(l1 - m1);
        s0 += a0; s1 += a1;
        const float4* xs = (const float4*)(xh + (size_t)s * 256);
        float4 v0 = __ldg(xs + lane);        // head0: floats [lane*4, +4)
        float4 v1 = __ldg(xs + lane + 32);   // head1
        f0[0] = fmaf(a0, v0.x, f0[0]); f0[1] = fmaf(a0, v0.y, f0[1]);
        f0[2] = fmaf(a0, v0.z, f0[2]); f0[3] = fmaf(a0, v0.w, f0[3]);
        f1[0] = fmaf(a1, v1.x, f1[0]); f1[1] = fmaf(a1, v1.y, f1[1]);
        f1[2] = fmaf(a1, v1.z, f1[2]); f1[3] = fmaf(a1, v1.w, f1[3]);
    }
    float i0 = 1.0f / (s0 + 1e-16f), i1 = 1.0f / (s1 + 1e-16f);
    float4 o0, o1;
    const float4* b0 = (const float4*)bias;
    float4 bb0 = b0[lane], bb1 = b0[lane + 32];
    o0.x = f0[0] * i0 + bb0.x; o0.y = f0[1] * i0 + bb0.y;
    o0.z = f0[2] * i0 + bb0.z; o0.w = f0[3] * i0 + bb0.w;
    o1.x = f1[0] * i1 + bb1.x; o1.y = f1[1] * i1 + bb1.y;
    o1.z = f1[2] * i1 + bb1.z; o1.w = f1[3] * i1 + bb1.w;
    // ELU
    o0.x = o0.x > 0.f ? o0.x : expm1f(o0.x);
    o0.y = o0.y > 0.f ? o0.y : expm1f(o0.y);
    o0.z = o0.z > 0.f ? o0.z : expm1f(o0.z);
    o0.w = o0.w > 0.f ? o0.w : expm1f(o0.w);
    o1.x = o1.x > 0.f ? o1.x : expm1f(o1.x);
    o1.y = o1.y > 0.f ? o1.y : expm1f(o1.y);
    o1.z = o1.z > 0.f ? o1.z : expm1f(o1.z);
    o1.w = o1.w > 0.f ? o1.w : expm1f(o1.w);
    float4* op = (float4*)(out + (size_t)d * 256);
    op[lane] = o0;
    op[lane + 32] = o1;
}

// GAT head=1, ch=64; writes (agg + bias) * scale into out[d*ostride + ooff + c]
__global__ __launch_bounds__(256) void gat_pull_1_64(
        const int* __restrict__ rs, const int* __restrict__ csr,
        const float* __restrict__ as_, const float* __restrict__ ad_,
        const float* __restrict__ xh, const float* __restrict__ bias,
        const float* __restrict__ scale, float* __restrict__ out,
        int ostride, int ooff) {
    int d = (blockIdx.x * blockDim.x + threadIdx.x) >> 5;
    int lane = threadIdx.x & 31;
    if (d >= NN) return;
    int beg = rs[d], end = rs[d + 1];
    float add = ad_[d];
    float m = -INFINITY;
    for (int j = beg + lane; j < end; j += 32) {
        int s = __ldg(&csr[j]);
        float l = as_[s] + add; l = l > 0.f ? l : 0.2f * l;
        m = fmaxf(m, l);
    }
#pragma unroll
    for (int o = 16; o; o >>= 1) m = fmaxf(m, __shfl_xor_sync(0xFFFFFFFFu, m, o));
    float ssum = 0.f, f0 = 0.f, f1 = 0.f;
    for (int j = beg; j < end; ++j) {
        int s = __ldg(&csr[j]);
        float l = as_[s] + add; l = l > 0.f ? l : 0.2f * l;
        float a = __expf(l - m);
        ssum += a;
        const float2* xs = (const float2*)(xh + (size_t)s * 64);
        float2 v = __ldg(xs + lane);
        f0 = fmaf(a, v.x, f0); f1 = fmaf(a, v.y, f1);
    }
    float sc = scale[0];
    float inv = 1.0f / (ssum + 1e-16f);
    float2 o;
    o.x = (f0 * inv + bias[lane * 2 + 0]) * sc;
    o.y = (f1 * inv + bias[lane * 2 + 1]) * sc;
    ((float2*)(out + (size_t)d * ostride + ooff))[lane] = o;
}

// ---------------------------------------------------------------------------
// GCN pull: one warp per destination node, fused bias/relu.
// ---------------------------------------------------------------------------
__global__ __launch_bounds__(256) void gcn_pull_128(
        const int* __restrict__ rs, const int* __restrict__ csr,
        const float* __restrict__ dinv, const float* __restrict__ xw,
        const float* __restrict__ bias, float* __restrict__ out, int relu) {
    int d = (blockIdx.x * blockDim.x + threadIdx.x) >> 5;
    int lane = threadIdx.x & 31;
    if (d >= NN) return;
    int beg = rs[d], end = rs[d + 1];
    float dd = dinv[d];
    float f[4] = {0.f, 0.f, 0.f, 0.f};
    for (int j = beg; j < end; ++j) {
        int s = __ldg(&csr[j]);
        float nrm = __ldg(&dinv[s]) * dd;
        float4 v = __ldg((const float4*)(xw + (size_t)s * 128) + lane);
        f[0] = fmaf(nrm, v.x, f[0]); f[1] = fmaf(nrm, v.y, f[1]);
        f[2] = fmaf(nrm, v.z, f[2]); f[3] = fmaf(nrm, v.w, f[3]);
    }
    float4 bb = ((const float4*)bias)[lane];
    float4 o;
    o.x = f[0] + bb.x; o.y = f[1] + bb.y; o.z = f[2] + bb.z; o.w = f[3] + bb.w;
    if (relu) {
        o.x = fmaxf(o.x, 0.f); o.y = fmaxf(o.y, 0.f);
        o.z = fmaxf(o.z, 0.f); o.w = fmaxf(o.w, 0.f);
    }
    ((float4*)(out + (size_t)d * 128))[lane] = o;
}

// GCN ch=64; writes (agg + bias) * scale into out[d*ostride + ooff + c]
__global__ __launch_bounds__(256) void gcn_pull_64(
        const int* __restrict__ rs, const int* __restrict__ csr,
        const float* __restrict__ dinv, const float* __restrict__ xw,
        const float* __restrict__ bias, const float* __restrict__ scale,
        float* __restrict__ out, int ostride, int ooff) {
    int d = (blockIdx.x * blockDim.x + threadIdx.x) >> 5;
    int lane = threadIdx.x & 31;
    if (d >= NN) return;
    int beg = rs[d], end = rs[d + 1];
    float dd = dinv[d];
    float f0 = 0.f, f1 = 0.f;
    for (int j = beg; j < end; ++j) {
        int s = __ldg(&csr[j]);
        float nrm = __ldg(&dinv[s]) * dd;
        float2 v = __ldg((const float2*)(xw + (size_t)s * 64) + lane);
        f0 = fmaf(nrm, v.x, f0); f1 = fmaf(nrm, v.y, f1);
    }
    float sc = scale[0];
    float2 o;
    o.x = (f0 + bias[lane * 2 + 0]) * sc;
    o.y = (f1 + bias[lane * 2 + 1]) * sc;
    ((float2*)(out + (size_t)d * ostride + ooff))[lane] = o;
}

// ---------------------------------------------------------------------------
static inline int cdiv(int a, int b) { return (a + b - 1) / b; }

extern "C" void kernel_launch(void* const* d_in, const int* in_sizes, int n_in,
                              void* d_out, int out_size) {
    const float* x      = (const float*)d_in[0];
    const int*   src    = (const int*)d_in[1];
    const int    E      = in_sizes[1] / 2;
    const int*   dst    = src + E;
    const float* gat1_W = (const float*)d_in[2];
    const float* att_s1 = (const float*)d_in[3];
    const float* att_d1 = (const float*)d_in[4];
    const float* gat1_b = (const float*)d_in[5];
    const float* gat2_W = (const float*)d_in[6];
    const float* att_s2 = (const float*)d_in[7];
    const float* att_d2 = (const float*)d_in[8];
    const float* gat2_b = (const float*)d_in[9];
    const float* gcn1_W = (const float*)d_in[10];
    const float* gcn1_b = (const float*)d_in[11];
    const float* gcn2_W = (const float*)d_in[12];
    const float* gcn2_b = (const float*)d_in[13];
    const float* lin1_W = (const float*)d_in[14];
    const float* lin1_b = (const float*)d_in[15];
    const float* lin2_W = (const float*)d_in[16];
    const float* lin2_b = (const float*)d_in[17];
    const float* lin3_W = (const float*)d_in[18];
    const float* lin3_b = (const float*)d_in[19];
    const float* wt     = (const float*)d_in[20];
    const float* wc     = (const float*)d_in[21];

    const int Etot = E + NN;

    float *xh1, *acc1, *as1, *ad1, *xh2, *as2, *ad2;
    float *xw1, *gcn1, *xw2, *dinv, *cat, *y1, *y2;
    int *counts, *rsp, *cursor, *csr;
    cudaGetSymbolAddress((void**)&xh1, g_xh1);
    cudaGetSymbolAddress((void**)&acc1, g_acc1);
    cudaGetSymbolAddress((void**)&as1, g_as1);
    cudaGetSymbolAddress((void**)&ad1, g_ad1);
    cudaGetSymbolAddress((void**)&xh2, g_xh2);
    cudaGetSymbolAddress((void**)&as2, g_as2);
    cudaGetSymbolAddress((void**)&ad2, g_ad2);
    cudaGetSymbolAddress((void**)&xw1, g_xw1);
    cudaGetSymbolAddress((void**)&gcn1, g_gcn1);
    cudaGetSymbolAddress((void**)&xw2, g_xw2);
    cudaGetSymbolAddress((void**)&dinv, g_dinv);
    cudaGetSymbolAddress((void**)&cat, g_cat);
    cudaGetSymbolAddress((void**)&y1, g_y1);
    cudaGetSymbolAddress((void**)&y2, g_y2);
    cudaGetSymbolAddress((void**)&counts, g_counts);
    cudaGetSymbolAddress((void**)&rsp, g_rs);
    cudaGetSymbolAddress((void**)&cursor, g_cursor);
    cudaGetSymbolAddress((void**)&csr, g_csr);

    const int TB = 256;

    // ---- CSR build (dst-grouped src list) ----
    zero_int_kernel<<<cdiv(NN, TB), TB>>>(counts, NN);
    hist_kernel<<<cdiv(Etot, TB), TB>>>(dst, counts, E, Etot);
    scan_kernel<<<1, 1024>>>(counts, rsp, NN);
    copy_int_kernel<<<cdiv(NN, TB), TB>>>(rsp, cursor, NN);
    csr_fill_kernel<<<cdiv(Etot, TB), TB>>>(src, dst, cursor, csr, E, Etot);
    dinv_kernel<<<cdiv(NN, TB), TB>>>(counts, dinv, NN);

    // ---- dense projections from x ----
    gemm2_kernel<<<dim3(256 / GBN, NN / GBM), 320>>>(x, gat1_W, nullptr, xh1, NN, 256, 128);
    gemm2_kernel<<<dim3(128 / GBN, NN / GBM), 320>>>(x, gcn1_W, nullptr, xw1, NN, 128, 128);

    // ---- GAT layer 1 (heads=2, ch=128) ----
    att_kernel<<<cdiv(NN * 2 * 32, TB), TB>>>(xh1, att_s1, att_d1, as1, ad1, NN * 2, 2, 128);
    gat_pull_2_128<<<cdiv(NN * 32, TB), TB>>>(rsp, csr, as1, ad1, xh1, gat1_b, acc1);

    // ---- GAT layer 2 (heads=1, ch=64) -> cat[:, 64:128] * wt ----
    gemm2_kernel<<<dim3(64 / GBN, NN / GBM), 320>>>(acc1, gat2_W, nullptr, xh2, NN, 64, 256);
    att_kernel<<<cdiv(NN * 32, TB), TB>>>(xh2, att_s2, att_d2, as2, ad2, NN, 1, 64);
    gat_pull_1_64<<<cdiv(NN * 32, TB), TB>>>(rsp, csr, as2, ad2, xh2, gat2_b, wt, cat, 128, 64);

    // ---- GCN layer 1 (relu fused) ----
    gcn_pull_128<<<cdiv(NN * 32, TB), TB>>>(rsp, csr, dinv, xw1, gcn1_b, gcn1, 1);

    // ---- GCN layer 2 -> cat[:, 0:64] * wc ----
    gemm2_kernel<<<dim3(64 / GBN, NN / GBM), 320>>>(gcn1, gcn2_W, nullptr, xw2, NN, 64, 128);
    gcn_pull_64<<<cdiv(NN * 32, TB), TB>>>(rsp, csr, dinv, xw2, gcn2_b, wc, cat, 128, 0);

    // ---- MLP head ----
    gemm2_kernel<<<dim3(256 / GBN, NN / GBM), 320>>>(cat, lin1_W, lin1_b, y1, NN, 256, 128);
    gemm2_kernel<<<dim3(128 / GBN, NN / GBM), 320>>>(y1, lin2_W, lin2_b, y2, NN, 128, 256);
    gemm2_kernel<<<dim3(64 / GBN, NN / GBM), 320>>>(y2, lin3_W, lin3_b, (float*)d_out, NN, 64, 128);
}